// round 11
// baseline (speedup 1.0000x reference)
#include <cuda_runtime.h>

#define NPTS 4096
#define TPB 256
#define ITILES 8             // 8 i-tiles x 512 i each (2 queries/thread)
#define JCHUNKS 74           // 8*74 = 592 blocks = exactly one wave @ 4 CTAs/SM (148 SMs)
#define CHUNK 56             // 74*56 = 4144 >= 4096, padded, branch-free
#define NBLOCKS (ITILES * JCHUNKS)
#define FING 128             // finalize: 128 blocks x 32 i's (lane = i)

__device__ float4 g_pden[JCHUNKS * NPTS];
__device__ float4 g_pnum[JCHUNKS * NPTS];
__device__ unsigned g_ctr  = 0;
__device__ unsigned g_done = 0;

// pack two f32 into f16x2: hi = first operand, lo = second
__device__ __forceinline__ unsigned packh2(float hi, float lo) {
    unsigned r;
    asm("cvt.rn.f16x2.f32 %0, %1, %2;" : "=r"(r) : "f"(hi), "f"(lo));
    return r;
}
// dual exponential: one MUFU op evaluates both packed halves
__device__ __forceinline__ unsigned ex2h2(unsigned v) {
    unsigned r;
    asm("ex2.approx.f16x2 %0, %1;" : "=r"(r) : "r"(v));
    return r;
}
__device__ __forceinline__ void unpackh2(unsigned v, float& hi, float& lo) {
    asm("{ .reg .b16 l, h;\n\t"
        "  mov.b32 {l, h}, %2;\n\t"
        "  cvt.f32.f16 %0, h;\n\t"
        "  cvt.f32.f16 %1, l; }"
        : "=f"(hi), "=f"(lo) : "r"(v));
}
__device__ __forceinline__ float ex2f_h(float g) {   // scalar via the same f16 path
    float hi, lo;
    unpackh2(ex2h2(packh2(g, g)), hi, lo);
    return hi;                                       // halves identical
}
// fixed fma order so hot loop, prep and finalize produce identical bits
__device__ __forceinline__ float dotw(float4 r, const float* __restrict__ W, int c) {
    float d = r.x * __ldg(W + c*4 + 0);
    d = fmaf(r.y, __ldg(W + c*4 + 1), d);
    d = fmaf(r.z, __ldg(W + c*4 + 2), d);
    d = fmaf(r.w, __ldg(W + c*4 + 3), d);
    return d;
}

// k'_{j,i,c} = 2^{a_j*(2 b_i) - a_j^2}; per-i factor 2^{-b_i^2} cancels in the ratio.
// s = sqrt(0.5*log2 e)/h. Exponentials evaluated pairwise with ex2.approx.f16x2.
__global__ void __launch_bounds__(TPB, 4) fused_kernel(
    const float* __restrict__ x,   // [4096,4]
    const float* __restrict__ tx,  // [4096,4]
    const float* __restrict__ Y,   // [4096,3]
    const float* __restrict__ W,   // [3,4]
    const float* __restrict__ h,   // [1]
    float* __restrict__ out)       // [4096,3]
{
    __shared__ float4 sA[CHUNK], sQ[CHUNK], sY[CHUNK];   // sQ holds -a^2

    const int tid = threadIdx.x, bx = blockIdx.x, by = blockIdx.y;
    const float s  = sqrtf(0.5f * 1.44269504088896340736f) / __ldg(h);
    const float s2 = s + s;

    // ---- prep this block's j-chunk into smem (tid < CHUNK, one row each) ----
    if (tid < CHUNK) {
        int j = by * CHUNK + tid;
        if (j < NPTS) {
            float4 xt = __ldg(reinterpret_cast<const float4*>(tx) + j);
            float a0 = dotw(xt, W, 0) * s;
            float a1 = dotw(xt, W, 1) * s;
            float a2 = dotw(xt, W, 2) * s;
            sA[tid] = make_float4(a0, a1, a2, 0.f);
            sQ[tid] = make_float4(-(a0*a0), -(a1*a1), -(a2*a2), 0.f);
            sY[tid] = make_float4(__ldg(Y+3*j), __ldg(Y+3*j+1), __ldg(Y+3*j+2), 0.f);
        } else {
            sA[tid] = make_float4(0.f, 0.f, 0.f, 0.f);
            sQ[tid] = make_float4(-3e38f, -3e38f, -3e38f, 0.f); // -> f16 -inf -> ex2 = 0
            sY[tid] = make_float4(0.f, 0.f, 0.f, 0.f);
        }
    }

    // ---- two query points per thread ----
    const int iA = bx * (2*TPB) + tid;
    const int iB = iA + TPB;
    float4 xqA = __ldg(reinterpret_cast<const float4*>(x) + iA);
    float4 xqB = __ldg(reinterpret_cast<const float4*>(x) + iB);
    const float tA0 = dotw(xqA,W,0)*s2, tA1 = dotw(xqA,W,1)*s2, tA2 = dotw(xqA,W,2)*s2;
    const float tB0 = dotw(xqB,W,0)*s2, tB1 = dotw(xqB,W,1)*s2, tB2 = dotw(xqB,W,2)*s2;
    __syncthreads();

    // ---- hot loop: 3 MUFU per j (each ex2.f16x2 serves queries A+B) ----
    float dA0=0.f,dA1=0.f,dA2=0.f, nA0=0.f,nA1=0.f,nA2=0.f;
    float dB0=0.f,dB1=0.f,dB2=0.f, nB0=0.f,nB1=0.f,nB2=0.f;
#pragma unroll 4
    for (int t = 0; t < CHUNK; ++t) {
        float4 a = sA[t];   // broadcast LDS.128
        float4 q = sQ[t];
        float4 y = sY[t];
        unsigned e0 = ex2h2(packh2(fmaf(a.x, tA0, q.x), fmaf(a.x, tB0, q.x)));
        unsigned e1 = ex2h2(packh2(fmaf(a.y, tA1, q.y), fmaf(a.y, tB1, q.y)));
        unsigned e2 = ex2h2(packh2(fmaf(a.z, tA2, q.z), fmaf(a.z, tB2, q.z)));
        float eA, eB;
        unpackh2(e0, eA, eB);
        dA0 += eA; nA0 = fmaf(eA, y.x, nA0);
        dB0 += eB; nB0 = fmaf(eB, y.x, nB0);
        unpackh2(e1, eA, eB);
        dA1 += eA; nA1 = fmaf(eA, y.y, nA1);
        dB1 += eB; nB1 = fmaf(eB, y.y, nB1);
        unpackh2(e2, eA, eB);
        dA2 += eA; nA2 = fmaf(eA, y.z, nA2);
        dB2 += eB; nB2 = fmaf(eB, y.z, nB2);
    }
    g_pden[by*NPTS + iA] = make_float4(dA0, dA1, dA2, 0.f);
    g_pnum[by*NPTS + iA] = make_float4(nA0, nA1, nA2, 0.f);
    g_pden[by*NPTS + iB] = make_float4(dB0, dB1, dB2, 0.f);
    g_pnum[by*NPTS + iB] = make_float4(nB0, nB1, nB2, 0.f);

    // ---- publish + device-wide ticket barrier (grid = exactly one wave) ----
    __threadfence();
    __syncthreads();
    if (tid == 0) {
        atomicAdd(&g_ctr, 1u);
        while (*((volatile unsigned*)&g_ctr) < NBLOCKS) __nanosleep(32);
    }
    __syncthreads();
    __threadfence();  // acquire

    // ---- finalize: first FING blocks, warp0 only, lane = i (coalesced) ----
    const int flat = by * ITILES + bx;
    if (flat < FING && tid < 32) {
        const int i = flat * 32 + tid;
        float D0=0.f,D1=0.f,D2=0.f, N0=0.f,N1=0.f,N2=0.f;
#pragma unroll 2
        for (int z = 0; z < JCHUNKS; ++z) {
            float4 pd = g_pden[z*NPTS + i];
            float4 pn = g_pnum[z*NPTS + i];
            D0 += pd.x; D1 += pd.y; D2 += pd.z;
            N0 += pn.x; N1 += pn.y; N2 += pn.z;
        }
        // self-pair (leave-one-out): identical fp16 ex2 path -> bit-identical value
        float4 xt = __ldg(reinterpret_cast<const float4*>(tx) + i);
        float4 xq = __ldg(reinterpret_cast<const float4*>(x) + i);
        float a0 = dotw(xt,W,0)*s,  a1 = dotw(xt,W,1)*s,  a2 = dotw(xt,W,2)*s;
        float t0 = dotw(xq,W,0)*s2, t1 = dotw(xq,W,1)*s2, t2 = dotw(xq,W,2)*s2;
        float k0 = ex2f_h(fmaf(a0, t0, -(a0*a0)));
        float k1 = ex2f_h(fmaf(a1, t1, -(a1*a1)));
        float k2 = ex2f_h(fmaf(a2, t2, -(a2*a2)));
        float y0 = __ldg(Y+3*i), y1 = __ldg(Y+3*i+1), y2 = __ldg(Y+3*i+2);
        out[3*i+0] = (N0 - k0*y0) / (D0 - k0);
        out[3*i+1] = (N1 - k1*y1) / (D1 - k1);
        out[3*i+2] = (N2 - k2*y2) / (D2 - k2);
    }

    // ---- last block resets counters -> stateless across graph replays ----
    __syncthreads();
    if (tid == 0) {
        unsigned v = atomicAdd(&g_done, 1u);
        if (v == NBLOCKS - 1) { g_ctr = 0; g_done = 0; __threadfence(); }
    }
}

extern "C" void kernel_launch(void* const* d_in, const int* in_sizes, int n_in,
                              void* d_out, int out_size) {
    const float* x  = (const float*)d_in[0];
    const float* tx = (const float*)d_in[1];
    const float* Y  = (const float*)d_in[2];
    const float* W  = (const float*)d_in[3];
    const float* h  = (const float*)d_in[4];
    float* out = (float*)d_out;

    fused_kernel<<<dim3(ITILES, JCHUNKS), TPB>>>(x, tx, Y, W, h, out);
}

// round 14
// speedup vs baseline: 1.0762x; 1.0762x over previous
#include <cuda_runtime.h>

#define NPTS 4096
#define TPB 256
#define ITILES 8             // 8 i-tiles x 512 i each (2 queries/thread)
#define JCHUNKS 74           // 8*74 = 592 blocks = exactly one wave @ 4 CTAs/SM (148 SMs)
#define CHUNK 56             // 2 groups x 28 j; 74*56 = 4144 >= 4096, padded
#define GROUPS 2
#define GJ 28                // j per f16-denominator group (worst-case sum ~1100 << 65504)
#define NBLOCKS (ITILES * JCHUNKS)
#define FING 128             // finalize: 128 blocks x 32 i's (lane = i)

__device__ float4 g_pden[JCHUNKS * NPTS];
__device__ float4 g_pnum[JCHUNKS * NPTS];
__device__ unsigned g_ctr  = 0;
__device__ unsigned g_done = 0;

// ---- f16 helpers (pack/ex2/unpack conventions identical to validated R11) ----
__device__ __forceinline__ unsigned packh2(float hi, float lo) {
    unsigned r;
    asm("cvt.rn.f16x2.f32 %0, %1, %2;" : "=r"(r) : "f"(hi), "f"(lo));
    return r;
}
__device__ __forceinline__ unsigned ex2h2(unsigned v) {   // dual exponential, one MUFU op
    unsigned r;
    asm("ex2.approx.f16x2 %0, %1;" : "=r"(r) : "r"(v));
    return r;
}
__device__ __forceinline__ void unpackh2(unsigned v, float& hi, float& lo) {
    asm("{ .reg .b16 l, h;\n\t"
        "  mov.b32 {l, h}, %2;\n\t"
        "  cvt.f32.f16 %0, h;\n\t"
        "  cvt.f32.f16 %1, l; }"
        : "=f"(hi), "=f"(lo) : "r"(v));
}
__device__ __forceinline__ unsigned hadd2(unsigned a, unsigned b) {
    unsigned r; asm("add.rn.f16x2 %0, %1, %2;" : "=r"(r) : "r"(a), "r"(b)); return r;
}
// split f16x2 word into (lo, hi) 16-bit halves (register-half aliasing, ~free)
__device__ __forceinline__ void split2(unsigned v, unsigned short& lo, unsigned short& hi) {
    asm("mov.b32 {%0, %1}, %2;" : "=h"(lo), "=h"(hi) : "r"(v));
}
__device__ __forceinline__ unsigned short f16of(float v) {
    unsigned short r; asm("cvt.rn.f16.f32 %0, %1;" : "=h"(r) : "f"(v)); return r;
}
__device__ __forceinline__ float f32of(unsigned short v) {
    float r; asm("cvt.f32.f16 %0, %1;" : "=f"(r) : "h"(v)); return r;
}
// mixed-precision FMA: f16*f16 + f32 -> f32 (product exact in f32)
__device__ __forceinline__ float mfma(unsigned short a, unsigned short b, float c) {
    float r;
    asm("fma.rn.f32.f16 %0, %1, %2, %3;" : "=f"(r) : "h"(a), "h"(b), "f"(c));
    return r;
}
__device__ __forceinline__ float ex2f_h(float g) {        // scalar via identical f16 path
    float hi, lo;
    unpackh2(ex2h2(packh2(g, g)), hi, lo);
    return hi;
}
// fixed fma order so hot loop, prep and finalize produce identical bits
__device__ __forceinline__ float dotw(float4 r, const float* __restrict__ W, int c) {
    float d = r.x * __ldg(W + c*4 + 0);
    d = fmaf(r.y, __ldg(W + c*4 + 1), d);
    d = fmaf(r.z, __ldg(W + c*4 + 2), d);
    d = fmaf(r.w, __ldg(W + c*4 + 3), d);
    return d;
}

// k'_{j,i,c} = 2^{a_j*(2 b_i) - a_j^2}; per-i factor 2^{-b_i^2} cancels in the ratio.
// f32 args -> dual f16 ex2 -> den: f16x2 HADD2 (folded 2x/chunk); num: mixed fma into f32.
__global__ void __launch_bounds__(TPB, 4) fused_kernel(
    const float* __restrict__ x,   // [4096,4]
    const float* __restrict__ tx,  // [4096,4]
    const float* __restrict__ Y,   // [4096,3]
    const float* __restrict__ W,   // [3,4]
    const float* __restrict__ h,   // [1]
    float* __restrict__ out)       // [4096,3]
{
    __shared__ float4 sA[CHUNK], sQ[CHUNK];              // sQ holds -a^2 (f32)
    __shared__ uint2  sYw[CHUNK];                         // {(y1|y0) f16x2, (0|y2) f16x2}

    const int tid = threadIdx.x, bx = blockIdx.x, by = blockIdx.y;
    const float s  = sqrtf(0.5f * 1.44269504088896340736f) / __ldg(h);
    const float s2 = s + s;

    // ---- prep this block's j-chunk into smem (tid < CHUNK, one row each) ----
    if (tid < CHUNK) {
        int j = by * CHUNK + tid;
        if (j < NPTS) {
            float4 xt = __ldg(reinterpret_cast<const float4*>(tx) + j);
            float a0 = dotw(xt, W, 0) * s;
            float a1 = dotw(xt, W, 1) * s;
            float a2 = dotw(xt, W, 2) * s;
            sA[tid] = make_float4(a0, a1, a2, 0.f);
            sQ[tid] = make_float4(-(a0*a0), -(a1*a1), -(a2*a2), 0.f);
            sYw[tid] = make_uint2(packh2(__ldg(Y+3*j+1), __ldg(Y+3*j+0)),   // hi=y1, lo=y0
                                  packh2(0.f,            __ldg(Y+3*j+2)));  // lo=y2
        } else {
            sA[tid] = make_float4(0.f, 0.f, 0.f, 0.f);
            sQ[tid] = make_float4(-3e38f, -3e38f, -3e38f, 0.f); // arg->-inf -> ex2=0
            sYw[tid] = make_uint2(0u, 0u);
        }
    }

    // ---- two query points per thread ----
    const int iA = bx * (2*TPB) + tid;
    const int iB = iA + TPB;
    float4 xqA = __ldg(reinterpret_cast<const float4*>(x) + iA);
    float4 xqB = __ldg(reinterpret_cast<const float4*>(x) + iB);
    const float tA0 = dotw(xqA,W,0)*s2, tA1 = dotw(xqA,W,1)*s2, tA2 = dotw(xqA,W,2)*s2;
    const float tB0 = dotw(xqB,W,0)*s2, tB1 = dotw(xqB,W,1)*s2, tB2 = dotw(xqB,W,2)*s2;
    __syncthreads();

    // ---- hot loop: 3 dual-EX2 per j; den f16x2 HADD2, num mixed-fma into f32 ----
    float DA0=0.f,DA1=0.f,DA2=0.f, DB0=0.f,DB1=0.f,DB2=0.f;
    float NA0=0.f,NA1=0.f,NA2=0.f, NB0=0.f,NB1=0.f,NB2=0.f;
#pragma unroll
    for (int g = 0; g < GROUPS; ++g) {
        unsigned hd0=0u, hd1=0u, hd2=0u;                 // packed (B|A) f16 den sums
#pragma unroll 4
        for (int u = 0; u < GJ; ++u) {
            const int t = g * GJ + u;
            float4 a = sA[t];          // broadcast LDS.128
            float4 q = sQ[t];
            uint2 yw = sYw[t];
            unsigned short y0, y1, y2, yj;
            split2(yw.x, y0, y1);
            split2(yw.y, y2, yj);
            unsigned e0 = ex2h2(packh2(fmaf(a.x, tA0, q.x), fmaf(a.x, tB0, q.x)));
            unsigned e1 = ex2h2(packh2(fmaf(a.y, tA1, q.y), fmaf(a.y, tB1, q.y)));
            unsigned e2 = ex2h2(packh2(fmaf(a.z, tA2, q.z), fmaf(a.z, tB2, q.z)));
            hd0 = hadd2(hd0, e0);
            hd1 = hadd2(hd1, e1);
            hd2 = hadd2(hd2, e2);
            unsigned short eB, eA;
            split2(e0, eB, eA); NA0 = mfma(eA, y0, NA0); NB0 = mfma(eB, y0, NB0);
            split2(e1, eB, eA); NA1 = mfma(eA, y1, NA1); NB1 = mfma(eB, y1, NB1);
            split2(e2, eB, eA); NA2 = mfma(eA, y2, NA2); NB2 = mfma(eB, y2, NB2);
        }
        float fa, fb;
        unpackh2(hd0, fa, fb); DA0 += fa; DB0 += fb;     // hi=A, lo=B
        unpackh2(hd1, fa, fb); DA1 += fa; DB1 += fb;
        unpackh2(hd2, fa, fb); DA2 += fa; DB2 += fb;
    }
    g_pden[by*NPTS + iA] = make_float4(DA0, DA1, DA2, 0.f);
    g_pnum[by*NPTS + iA] = make_float4(NA0, NA1, NA2, 0.f);
    g_pden[by*NPTS + iB] = make_float4(DB0, DB1, DB2, 0.f);
    g_pnum[by*NPTS + iB] = make_float4(NB0, NB1, NB2, 0.f);

    // ---- publish + device-wide ticket barrier (grid = exactly one wave) ----
    __threadfence();
    __syncthreads();
    if (tid == 0) {
        atomicAdd(&g_ctr, 1u);
        while (*((volatile unsigned*)&g_ctr) < NBLOCKS) __nanosleep(32);
    }
    __syncthreads();
    __threadfence();  // acquire

    // ---- finalize: first FING blocks, warp0 only, lane = i (coalesced) ----
    const int flat = by * ITILES + bx;
    if (flat < FING && tid < 32) {
        const int i = flat * 32 + tid;
        float D0=0.f,D1=0.f,D2=0.f, N0=0.f,N1=0.f,N2=0.f;
#pragma unroll 2
        for (int z = 0; z < JCHUNKS; ++z) {
            float4 pd = g_pden[z*NPTS + i];
            float4 pn = g_pnum[z*NPTS + i];
            D0 += pd.x; D1 += pd.y; D2 += pd.z;
            N0 += pn.x; N1 += pn.y; N2 += pn.z;
        }
        // self-pair (leave-one-out): identical f16 ex2 path; product of two f16s is
        // exact in f32, so num subtraction matches the in-loop mixed-fma term.
        float4 xt = __ldg(reinterpret_cast<const float4*>(tx) + i);
        float4 xq = __ldg(reinterpret_cast<const float4*>(x) + i);
        float a0 = dotw(xt,W,0)*s,  a1 = dotw(xt,W,1)*s,  a2 = dotw(xt,W,2)*s;
        float t0 = dotw(xq,W,0)*s2, t1 = dotw(xq,W,1)*s2, t2 = dotw(xq,W,2)*s2;
        float k0 = ex2f_h(fmaf(a0, t0, -(a0*a0)));
        float k1 = ex2f_h(fmaf(a1, t1, -(a1*a1)));
        float k2 = ex2f_h(fmaf(a2, t2, -(a2*a2)));
        float y0 = f32of(f16of(__ldg(Y+3*i+0)));
        float y1 = f32of(f16of(__ldg(Y+3*i+1)));
        float y2 = f32of(f16of(__ldg(Y+3*i+2)));
        out[3*i+0] = (N0 - k0*y0) / (D0 - k0);
        out[3*i+1] = (N1 - k1*y1) / (D1 - k1);
        out[3*i+2] = (N2 - k2*y2) / (D2 - k2);
    }

    // ---- last block resets counters -> stateless across graph replays ----
    __syncthreads();
    if (tid == 0) {
        unsigned v = atomicAdd(&g_done, 1u);
        if (v == NBLOCKS - 1) { g_ctr = 0; g_done = 0; __threadfence(); }
    }
}

extern "C" void kernel_launch(void* const* d_in, const int* in_sizes, int n_in,
                              void* d_out, int out_size) {
    const float* x  = (const float*)d_in[0];
    const float* tx = (const float*)d_in[1];
    const float* Y  = (const float*)d_in[2];
    const float* W  = (const float*)d_in[3];
    const float* h  = (const float*)d_in[4];
    float* out = (float*)d_out;

    fused_kernel<<<dim3(ITILES, JCHUNKS), TPB>>>(x, tx, Y, W, h, out);
}

// round 15
// speedup vs baseline: 1.1390x; 1.0584x over previous
#include <cuda_runtime.h>

#define NPTS 4096
#define TPB 256
#define ITILES 8             // 8 i-tiles x 512 i each (2 queries/thread)
#define JCHUNKS 74           // 8*74 = 592 blocks = exactly one wave @ 4 CTAs/SM (148 SMs)
#define CHUNK 56             // 74*56 = 4144 >= 4096, padded, branch-free
#define NBLOCKS (ITILES * JCHUNKS)
#define FING 128             // finalize: 128 blocks x 32 i's (lane = i)

__device__ float4 g_pden[JCHUNKS * NPTS];
__device__ float4 g_pnum[JCHUNKS * NPTS];
__device__ unsigned g_ctr  = 0;
__device__ unsigned g_done = 0;

__device__ __forceinline__ float ex2f(float x) {
    float y;
    asm("ex2.approx.ftz.f32 %0, %1;" : "=f"(y) : "f"(x));
    return y;
}
// fixed fma order so hot loop, prep and finalize produce identical bits
__device__ __forceinline__ float dotw(float4 r, const float* __restrict__ W, int c) {
    float d = r.x * __ldg(W + c*4 + 0);
    d = fmaf(r.y, __ldg(W + c*4 + 1), d);
    d = fmaf(r.z, __ldg(W + c*4 + 2), d);
    d = fmaf(r.w, __ldg(W + c*4 + 3), d);
    return d;
}

// k'_{j,i,c} = 2^{a_j*(2 b_i) - a_j^2}; the per-i factor 2^{-b_i^2} cancels in the ratio.
// s = sqrt(0.5*log2 e)/h. Hot cost per pair-channel: 1 FFMA + 1 EX2 + 1 FADD + 1 FFMA.
__global__ void __launch_bounds__(TPB, 4) fused_kernel(
    const float* __restrict__ x,   // [4096,4]
    const float* __restrict__ tx,  // [4096,4]
    const float* __restrict__ Y,   // [4096,3]
    const float* __restrict__ W,   // [3,4]
    const float* __restrict__ h,   // [1]
    float* __restrict__ out)       // [4096,3]
{
    __shared__ float4 sA[CHUNK], sQ[CHUNK], sY[CHUNK];   // sQ holds -a^2

    const int tid = threadIdx.x, bx = blockIdx.x, by = blockIdx.y;
    const float s  = sqrtf(0.5f * 1.44269504088896340736f) / __ldg(h);
    const float s2 = s + s;

    // ---- prep this block's j-chunk into smem (tid < CHUNK, one row each) ----
    if (tid < CHUNK) {
        int j = by * CHUNK + tid;
        if (j < NPTS) {
            float4 xt = __ldg(reinterpret_cast<const float4*>(tx) + j);
            float a0 = dotw(xt, W, 0) * s;
            float a1 = dotw(xt, W, 1) * s;
            float a2 = dotw(xt, W, 2) * s;
            sA[tid] = make_float4(a0, a1, a2, 0.f);
            sQ[tid] = make_float4(-(a0*a0), -(a1*a1), -(a2*a2), 0.f);
            sY[tid] = make_float4(__ldg(Y+3*j), __ldg(Y+3*j+1), __ldg(Y+3*j+2), 0.f);
        } else {
            sA[tid] = make_float4(0.f, 0.f, 0.f, 0.f);
            sQ[tid] = make_float4(-3e38f, -3e38f, -3e38f, 0.f); // ex2 -> 0
            sY[tid] = make_float4(0.f, 0.f, 0.f, 0.f);
        }
    }

    // ---- two query points per thread ----
    const int iA = bx * (2*TPB) + tid;
    const int iB = iA + TPB;
    float4 xqA = __ldg(reinterpret_cast<const float4*>(x) + iA);
    float4 xqB = __ldg(reinterpret_cast<const float4*>(x) + iB);
    const float tA0 = dotw(xqA,W,0)*s2, tA1 = dotw(xqA,W,1)*s2, tA2 = dotw(xqA,W,2)*s2;
    const float tB0 = dotw(xqB,W,0)*s2, tB1 = dotw(xqB,W,1)*s2, tB2 = dotw(xqB,W,2)*s2;
    __syncthreads();

    // ---- hot loop: each j-row feeds 6 EX2 (3 channels x 2 queries) ----
    float dA0=0.f,dA1=0.f,dA2=0.f, nA0=0.f,nA1=0.f,nA2=0.f;
    float dB0=0.f,dB1=0.f,dB2=0.f, nB0=0.f,nB1=0.f,nB2=0.f;
#pragma unroll 4
    for (int t = 0; t < CHUNK; ++t) {
        float4 a = sA[t];   // broadcast LDS.128
        float4 q = sQ[t];
        float4 y = sY[t];
        float e;
        e = ex2f(fmaf(a.x, tA0, q.x)); dA0 += e; nA0 = fmaf(e, y.x, nA0);
        e = ex2f(fmaf(a.y, tA1, q.y)); dA1 += e; nA1 = fmaf(e, y.y, nA1);
        e = ex2f(fmaf(a.z, tA2, q.z)); dA2 += e; nA2 = fmaf(e, y.z, nA2);
        e = ex2f(fmaf(a.x, tB0, q.x)); dB0 += e; nB0 = fmaf(e, y.x, nB0);
        e = ex2f(fmaf(a.y, tB1, q.y)); dB1 += e; nB1 = fmaf(e, y.y, nB1);
        e = ex2f(fmaf(a.z, tB2, q.z)); dB2 += e; nB2 = fmaf(e, y.z, nB2);
    }
    g_pden[by*NPTS + iA] = make_float4(dA0, dA1, dA2, 0.f);
    g_pnum[by*NPTS + iA] = make_float4(nA0, nA1, nA2, 0.f);
    g_pden[by*NPTS + iB] = make_float4(dB0, dB1, dB2, 0.f);
    g_pnum[by*NPTS + iB] = make_float4(nB0, nB1, nB2, 0.f);

    // ---- publish + device-wide ticket barrier (grid = exactly one wave) ----
    __threadfence();
    __syncthreads();
    if (tid == 0) {
        atomicAdd(&g_ctr, 1u);
        while (*((volatile unsigned*)&g_ctr) < NBLOCKS) __nanosleep(32);
    }
    __syncthreads();
    __threadfence();  // acquire

    // ---- finalize: first FING blocks, warp0 only, lane = i (coalesced) ----
    const int flat = by * ITILES + bx;
    if (flat < FING && tid < 32) {
        const int i = flat * 32 + tid;
        float D0=0.f,D1=0.f,D2=0.f, N0=0.f,N1=0.f,N2=0.f;
#pragma unroll 8
        for (int z = 0; z < JCHUNKS; ++z) {
            float4 pd = g_pden[z*NPTS + i];
            float4 pn = g_pnum[z*NPTS + i];
            D0 += pd.x; D1 += pd.y; D2 += pd.z;
            N0 += pn.x; N1 += pn.y; N2 += pn.z;
        }
        // self-pair (leave-one-out): bit-identical recompute of the loop term
        float4 xt = __ldg(reinterpret_cast<const float4*>(tx) + i);
        float4 xq = __ldg(reinterpret_cast<const float4*>(x) + i);
        float a0 = dotw(xt,W,0)*s,  a1 = dotw(xt,W,1)*s,  a2 = dotw(xt,W,2)*s;
        float t0 = dotw(xq,W,0)*s2, t1 = dotw(xq,W,1)*s2, t2 = dotw(xq,W,2)*s2;
        float k0 = ex2f(fmaf(a0, t0, -(a0*a0)));
        float k1 = ex2f(fmaf(a1, t1, -(a1*a1)));
        float k2 = ex2f(fmaf(a2, t2, -(a2*a2)));
        float y0 = __ldg(Y+3*i), y1 = __ldg(Y+3*i+1), y2 = __ldg(Y+3*i+2);
        out[3*i+0] = (N0 - k0*y0) / (D0 - k0);
        out[3*i+1] = (N1 - k1*y1) / (D1 - k1);
        out[3*i+2] = (N2 - k2*y2) / (D2 - k2);
    }

    // ---- last block resets counters -> stateless across graph replays ----
    __syncthreads();
    if (tid == 0) {
        unsigned v = atomicAdd(&g_done, 1u);
        if (v == NBLOCKS - 1) { g_ctr = 0; g_done = 0; __threadfence(); }
    }
}

extern "C" void kernel_launch(void* const* d_in, const int* in_sizes, int n_in,
                              void* d_out, int out_size) {
    const float* x  = (const float*)d_in[0];
    const float* tx = (const float*)d_in[1];
    const float* Y  = (const float*)d_in[2];
    const float* W  = (const float*)d_in[3];
    const float* h  = (const float*)d_in[4];
    float* out = (float*)d_out;

    fused_kernel<<<dim3(ITILES, JCHUNKS), TPB>>>(x, tx, Y, W, h, out);
}

// round 16
// speedup vs baseline: 1.6250x; 1.4267x over previous
#include <cuda_runtime.h>

#define NPTS 4096
#define TPB 256
#define ITILES 8             // i-tiles of 512 (2 i's per thread)
#define JCHUNKS 74           // 8*74 = 592 blocks = one wave @ 4 CTAs/SM on 148 SMs
#define CHUNK 56             // 74*56 = 4144 >= 4096, padded, branch-free
#define NBLOCKS (ITILES * JCHUNKS)
#define FINB 64              // fin blocks: 64 blocks x 64 i's x 4-way z-split

__device__ float4 g_pden[JCHUNKS * NPTS];
__device__ float4 g_pnum[JCHUNKS * NPTS];
__device__ unsigned g_ctr  = 0;
__device__ unsigned g_done = 0;

__device__ __forceinline__ float ex2f(float x) {
    float y;
    asm("ex2.approx.ftz.f32 %0, %1;" : "=f"(y) : "f"(x));
    return y;
}

// dot(row4, W[c*4..]) with a FIXED fma order so prep and fin produce identical bits
__device__ __forceinline__ float dotw(float4 r, const float* __restrict__ W, int c) {
    float d = r.x * __ldg(W + c*4 + 0);
    d = fmaf(r.y, __ldg(W + c*4 + 1), d);
    d = fmaf(r.z, __ldg(W + c*4 + 2), d);
    d = fmaf(r.w, __ldg(W + c*4 + 3), d);
    return d;
}

// k'_{j,i,c} = 2^{a_j*(2 b_i) - a_j^2}; the per-i factor 2^{-b^2} cancels in the ratio.
// s = sqrt(0.5*log2 e)/h. Hot cost per pair-channel: 1 FFMA + 1 EX2 + 1 FADD + 1 FFMA.
__global__ void __launch_bounds__(TPB, 4) fused_kernel(
    const float* __restrict__ x,   // [4096,4]
    const float* __restrict__ tx,  // [4096,4]
    const float* __restrict__ Y,   // [4096,3]
    const float* __restrict__ W,   // [3,4]
    const float* __restrict__ h,   // [1]
    float* __restrict__ out)       // [4096,3]
{
    __shared__ float4 sA[CHUNK], sQ[CHUNK], sY[CHUNK];
    __shared__ float sRed[3][FINB][8];   // fin z-split combine buffer

    const int tid = threadIdx.x;
    const float s  = sqrtf(0.5f * 1.44269504088896340736f) / __ldg(h);
    const float s2 = s + s;

    // ---- prep this block's j-chunk into smem (threads 0..CHUNK-1, one row each) ----
    const int j0 = blockIdx.y * CHUNK;
    if (tid < CHUNK) {
        int j = j0 + tid;
        if (j < NPTS) {
            float4 xt = __ldg(reinterpret_cast<const float4*>(tx) + j);
            float a0 = dotw(xt, W, 0) * s;
            float a1 = dotw(xt, W, 1) * s;
            float a2 = dotw(xt, W, 2) * s;
            sA[tid] = make_float4(a0, a1, a2, 0.f);
            sQ[tid] = make_float4(a0*a0, a1*a1, a2*a2, 0.f);
            sY[tid] = make_float4(__ldg(Y+3*j), __ldg(Y+3*j+1), __ldg(Y+3*j+2), 0.f);
        } else {
            sA[tid] = make_float4(0.f, 0.f, 0.f, 0.f);
            sQ[tid] = make_float4(3e38f, 3e38f, 3e38f, 0.f); // ex2(-3e38) -> 0
            sY[tid] = make_float4(0.f, 0.f, 0.f, 0.f);
        }
    }

    // ---- two query points per thread ----
    const int iA = blockIdx.x * (2*TPB) + tid;
    const int iB = iA + TPB;
    float4 xqA = __ldg(reinterpret_cast<const float4*>(x) + iA);
    float4 xqB = __ldg(reinterpret_cast<const float4*>(x) + iB);
    const float tA0 = dotw(xqA, W, 0) * s2, tA1 = dotw(xqA, W, 1) * s2, tA2 = dotw(xqA, W, 2) * s2;
    const float tB0 = dotw(xqB, W, 0) * s2, tB1 = dotw(xqB, W, 1) * s2, tB2 = dotw(xqB, W, 2) * s2;
    __syncthreads();

    // ---- hot loop: each j-row feeds 6 EX2 (3 channels x 2 queries) ----
    float dA0=0.f,dA1=0.f,dA2=0.f, nA0=0.f,nA1=0.f,nA2=0.f;
    float dB0=0.f,dB1=0.f,dB2=0.f, nB0=0.f,nB1=0.f,nB2=0.f;
#pragma unroll 4
    for (int t = 0; t < CHUNK; ++t) {
        float4 a = sA[t];   // broadcast LDS.128
        float4 q = sQ[t];
        float4 y = sY[t];
        float e;
        e = ex2f(fmaf(a.x, tA0, -q.x)); dA0 += e; nA0 = fmaf(e, y.x, nA0);
        e = ex2f(fmaf(a.y, tA1, -q.y)); dA1 += e; nA1 = fmaf(e, y.y, nA1);
        e = ex2f(fmaf(a.z, tA2, -q.z)); dA2 += e; nA2 = fmaf(e, y.z, nA2);
        e = ex2f(fmaf(a.x, tB0, -q.x)); dB0 += e; nB0 = fmaf(e, y.x, nB0);
        e = ex2f(fmaf(a.y, tB1, -q.y)); dB1 += e; nB1 = fmaf(e, y.y, nB1);
        e = ex2f(fmaf(a.z, tB2, -q.z)); dB2 += e; nB2 = fmaf(e, y.z, nB2);
    }
    g_pden[blockIdx.y * NPTS + iA] = make_float4(dA0, dA1, dA2, 0.f);
    g_pnum[blockIdx.y * NPTS + iA] = make_float4(nA0, nA1, nA2, 0.f);
    g_pden[blockIdx.y * NPTS + iB] = make_float4(dB0, dB1, dB2, 0.f);
    g_pnum[blockIdx.y * NPTS + iB] = make_float4(nB0, nB1, nB2, 0.f);

    // ---- publish partial: fence + ticket ----
    __threadfence();
    __syncthreads();
    if (tid == 0) atomicAdd(&g_ctr, 1u);

    // ---- finalize: first FINB blocks (flat order), 4-way z-split per i ----
    const int flat = blockIdx.y * ITILES + blockIdx.x;
    if (flat >= FINB) return;

    if (tid == 0) {
        while (*((volatile unsigned*)&g_ctr) < NBLOCKS) __nanosleep(32);
    }
    __syncthreads();
    __threadfence();  // acquire

    const int ii = tid & (FINB - 1);       // 0..63
    const int zg = tid >> 6;               // 0..3
    const int i  = flat * FINB + ii;
    const int z0 = zg * 19;
    const int z1 = min(JCHUNKS, z0 + 19);

    float D0=0.f,D1=0.f,D2=0.f, N0=0.f,N1=0.f,N2=0.f;
    for (int z = z0; z < z1; ++z) {
        float4 pd = g_pden[z * NPTS + i];
        float4 pn = g_pnum[z * NPTS + i];
        D0 += pd.x; D1 += pd.y; D2 += pd.z;
        N0 += pn.x; N1 += pn.y; N2 += pn.z;
    }
    if (zg > 0) {
        sRed[zg-1][ii][0] = D0; sRed[zg-1][ii][1] = D1; sRed[zg-1][ii][2] = D2;
        sRed[zg-1][ii][3] = N0; sRed[zg-1][ii][4] = N1; sRed[zg-1][ii][5] = N2;
    }
    __syncthreads();
    if (zg == 0) {
#pragma unroll
        for (int g = 0; g < 3; ++g) {
            D0 += sRed[g][ii][0]; D1 += sRed[g][ii][1]; D2 += sRed[g][ii][2];
            N0 += sRed[g][ii][3]; N1 += sRed[g][ii][4]; N2 += sRed[g][ii][5];
        }
        // self-pair (leave-one-out): bit-identical recompute of the in-loop term
        float4 xt = __ldg(reinterpret_cast<const float4*>(tx) + i);
        float4 xq = __ldg(reinterpret_cast<const float4*>(x) + i);
        float a0 = dotw(xt, W, 0) * s, a1 = dotw(xt, W, 1) * s, a2 = dotw(xt, W, 2) * s;
        float t0 = dotw(xq, W, 0) * s2, t1 = dotw(xq, W, 1) * s2, t2 = dotw(xq, W, 2) * s2;
        float k0 = ex2f(fmaf(a0, t0, -(a0*a0)));
        float k1 = ex2f(fmaf(a1, t1, -(a1*a1)));
        float k2 = ex2f(fmaf(a2, t2, -(a2*a2)));
        float y0 = __ldg(Y+3*i), y1 = __ldg(Y+3*i+1), y2 = __ldg(Y+3*i+2);
        out[3*i+0] = (N0 - k0*y0) / (D0 - k0);
        out[3*i+1] = (N1 - k1*y1) / (D1 - k1);
        out[3*i+2] = (N2 - k2*y2) / (D2 - k2);
    }

    // ---- reset counters for the next graph replay ----
    __syncthreads();
    if (tid == 0) {
        unsigned v = atomicAdd(&g_done, 1u);
        if (v == FINB - 1) { g_ctr = 0; g_done = 0; __threadfence(); }
    }
}

extern "C" void kernel_launch(void* const* d_in, const int* in_sizes, int n_in,
                              void* d_out, int out_size) {
    const float* x  = (const float*)d_in[0];
    const float* tx = (const float*)d_in[1];
    const float* Y  = (const float*)d_in[2];
    const float* W  = (const float*)d_in[3];
    const float* h  = (const float*)d_in[4];
    float* out = (float*)d_out;

    fused_kernel<<<dim3(ITILES, JCHUNKS), TPB>>>(x, tx, Y, W, h, out);
}

// round 17
// speedup vs baseline: 1.6497x; 1.0152x over previous
#include <cuda_runtime.h>

#define NPTS 4096
#define TPB 256
#define ITILES 8             // i-tiles of 512 (2 i's per thread)
#define JCHUNKS 74           // 8*74 = 592 blocks = one wave @ 4 CTAs/SM on 148 SMs
#define CHUNK 56             // 74*56 = 4144 >= 4096, padded, branch-free
#define NBLOCKS (ITILES * JCHUNKS)
#define FINB 64              // fin blocks: 64 blocks x 64 i's x 4-way z-split

__device__ float4 g_pden[JCHUNKS * NPTS];
__device__ float4 g_pnum[JCHUNKS * NPTS];
__device__ unsigned g_ctr  = 0;
__device__ unsigned g_done = 0;

__device__ __forceinline__ float ex2f(float x) {
    float y;
    asm("ex2.approx.ftz.f32 %0, %1;" : "=f"(y) : "f"(x));
    return y;
}

// dot(row4, W[c*4..]) with a FIXED fma order so prep and fin produce identical bits
__device__ __forceinline__ float dotw(float4 r, const float* __restrict__ W, int c) {
    float d = r.x * __ldg(W + c*4 + 0);
    d = fmaf(r.y, __ldg(W + c*4 + 1), d);
    d = fmaf(r.z, __ldg(W + c*4 + 2), d);
    d = fmaf(r.w, __ldg(W + c*4 + 3), d);
    return d;
}

// k'_{j,i,c} = 2^{a_j*(2 b_i) - a_j^2}; the per-i factor 2^{-b^2} cancels in the ratio.
// s = sqrt(0.5*log2 e)/h. Hot cost per pair-channel: 1 FFMA + 1 EX2 + 1 FADD + 1 FFMA.
__global__ void __launch_bounds__(TPB, 4) fused_kernel(
    const float* __restrict__ x,   // [4096,4]
    const float* __restrict__ tx,  // [4096,4]
    const float* __restrict__ Y,   // [4096,3]
    const float* __restrict__ W,   // [3,4]
    const float* __restrict__ h,   // [1]
    float* __restrict__ out)       // [4096,3]
{
    __shared__ float4 sA[CHUNK], sQ[CHUNK], sY[CHUNK];
    __shared__ float sRed[3][FINB][8];   // fin z-split combine buffer

    const int tid = threadIdx.x;
    const float s  = sqrtf(0.5f * 1.44269504088896340736f) / __ldg(h);
    const float s2 = s + s;

    // ---- prep this block's j-chunk into smem (threads 0..CHUNK-1, one row each) ----
    const int j0 = blockIdx.y * CHUNK;
    if (tid < CHUNK) {
        int j = j0 + tid;
        if (j < NPTS) {
            float4 xt = __ldg(reinterpret_cast<const float4*>(tx) + j);
            float a0 = dotw(xt, W, 0) * s;
            float a1 = dotw(xt, W, 1) * s;
            float a2 = dotw(xt, W, 2) * s;
            sA[tid] = make_float4(a0, a1, a2, 0.f);
            sQ[tid] = make_float4(a0*a0, a1*a1, a2*a2, 0.f);
            sY[tid] = make_float4(__ldg(Y+3*j), __ldg(Y+3*j+1), __ldg(Y+3*j+2), 0.f);
        } else {
            sA[tid] = make_float4(0.f, 0.f, 0.f, 0.f);
            sQ[tid] = make_float4(3e38f, 3e38f, 3e38f, 0.f); // ex2(-3e38) -> 0
            sY[tid] = make_float4(0.f, 0.f, 0.f, 0.f);
        }
    }

    // ---- two query points per thread ----
    const int iA = blockIdx.x * (2*TPB) + tid;
    const int iB = iA + TPB;
    float4 xqA = __ldg(reinterpret_cast<const float4*>(x) + iA);
    float4 xqB = __ldg(reinterpret_cast<const float4*>(x) + iB);
    const float tA0 = dotw(xqA, W, 0) * s2, tA1 = dotw(xqA, W, 1) * s2, tA2 = dotw(xqA, W, 2) * s2;
    const float tB0 = dotw(xqB, W, 0) * s2, tB1 = dotw(xqB, W, 1) * s2, tB2 = dotw(xqB, W, 2) * s2;
    __syncthreads();

    // ---- hot loop: each j-row feeds 6 EX2 (3 channels x 2 queries) ----
    float dA0=0.f,dA1=0.f,dA2=0.f, nA0=0.f,nA1=0.f,nA2=0.f;
    float dB0=0.f,dB1=0.f,dB2=0.f, nB0=0.f,nB1=0.f,nB2=0.f;
#pragma unroll 4
    for (int t = 0; t < CHUNK; ++t) {
        float4 a = sA[t];   // broadcast LDS.128
        float4 q = sQ[t];
        float4 y = sY[t];
        float e;
        e = ex2f(fmaf(a.x, tA0, -q.x)); dA0 += e; nA0 = fmaf(e, y.x, nA0);
        e = ex2f(fmaf(a.y, tA1, -q.y)); dA1 += e; nA1 = fmaf(e, y.y, nA1);
        e = ex2f(fmaf(a.z, tA2, -q.z)); dA2 += e; nA2 = fmaf(e, y.z, nA2);
        e = ex2f(fmaf(a.x, tB0, -q.x)); dB0 += e; nB0 = fmaf(e, y.x, nB0);
        e = ex2f(fmaf(a.y, tB1, -q.y)); dB1 += e; nB1 = fmaf(e, y.y, nB1);
        e = ex2f(fmaf(a.z, tB2, -q.z)); dB2 += e; nB2 = fmaf(e, y.z, nB2);
    }
    g_pden[blockIdx.y * NPTS + iA] = make_float4(dA0, dA1, dA2, 0.f);
    g_pnum[blockIdx.y * NPTS + iA] = make_float4(nA0, nA1, nA2, 0.f);
    g_pden[blockIdx.y * NPTS + iB] = make_float4(dB0, dB1, dB2, 0.f);
    g_pnum[blockIdx.y * NPTS + iB] = make_float4(nB0, nB1, nB2, 0.f);

    // ---- publish partial: fence + ticket ----
    __threadfence();
    __syncthreads();
    if (tid == 0) atomicAdd(&g_ctr, 1u);

    // ---- finalize: first FINB blocks (flat order), 4-way z-split per i ----
    const int flat = blockIdx.y * ITILES + blockIdx.x;
    if (flat >= FINB) return;

    if (tid == 0) {
        while (*((volatile unsigned*)&g_ctr) < NBLOCKS) __nanosleep(32);
    }
    __syncthreads();
    __threadfence();  // acquire

    const int ii = tid & (FINB - 1);       // 0..63
    const int zg = tid >> 6;               // 0..3
    const int i  = flat * FINB + ii;
    const int z0 = zg * 19;
    const int z1 = min(JCHUNKS, z0 + 19);

    float D0=0.f,D1=0.f,D2=0.f, N0=0.f,N1=0.f,N2=0.f;
    for (int z = z0; z < z1; ++z) {
        float4 pd = g_pden[z * NPTS + i];
        float4 pn = g_pnum[z * NPTS + i];
        D0 += pd.x; D1 += pd.y; D2 += pd.z;
        N0 += pn.x; N1 += pn.y; N2 += pn.z;
    }
    if (zg > 0) {
        sRed[zg-1][ii][0] = D0; sRed[zg-1][ii][1] = D1; sRed[zg-1][ii][2] = D2;
        sRed[zg-1][ii][3] = N0; sRed[zg-1][ii][4] = N1; sRed[zg-1][ii][5] = N2;
    }
    __syncthreads();
    if (zg == 0) {
#pragma unroll
        for (int g = 0; g < 3; ++g) {
            D0 += sRed[g][ii][0]; D1 += sRed[g][ii][1]; D2 += sRed[g][ii][2];
            N0 += sRed[g][ii][3]; N1 += sRed[g][ii][4]; N2 += sRed[g][ii][5];
        }
        // self-pair (leave-one-out): bit-identical recompute of the in-loop term
        float4 xt = __ldg(reinterpret_cast<const float4*>(tx) + i);
        float4 xq = __ldg(reinterpret_cast<const float4*>(x) + i);
        float a0 = dotw(xt, W, 0) * s, a1 = dotw(xt, W, 1) * s, a2 = dotw(xt, W, 2) * s;
        float t0 = dotw(xq, W, 0) * s2, t1 = dotw(xq, W, 1) * s2, t2 = dotw(xq, W, 2) * s2;
        float k0 = ex2f(fmaf(a0, t0, -(a0*a0)));
        float k1 = ex2f(fmaf(a1, t1, -(a1*a1)));
        float k2 = ex2f(fmaf(a2, t2, -(a2*a2)));
        float y0 = __ldg(Y+3*i), y1 = __ldg(Y+3*i+1), y2 = __ldg(Y+3*i+2);
        out[3*i+0] = (N0 - k0*y0) / (D0 - k0);
        out[3*i+1] = (N1 - k1*y1) / (D1 - k1);
        out[3*i+2] = (N2 - k2*y2) / (D2 - k2);
    }

    // ---- reset counters for the next graph replay ----
    __syncthreads();
    if (tid == 0) {
        unsigned v = atomicAdd(&g_done, 1u);
        if (v == FINB - 1) { g_ctr = 0; g_done = 0; __threadfence(); }
    }
}

extern "C" void kernel_launch(void* const* d_in, const int* in_sizes, int n_in,
                              void* d_out, int out_size) {
    const float* x  = (const float*)d_in[0];
    const float* tx = (const float*)d_in[1];
    const float* Y  = (const float*)d_in[2];
    const float* W  = (const float*)d_in[3];
    const float* h  = (const float*)d_in[4];
    float* out = (float*)d_out;

    fused_kernel<<<dim3(ITILES, JCHUNKS), TPB>>>(x, tx, Y, W, h, out);
}